// round 15
// baseline (speedup 1.0000x reference)
#include <cuda_runtime.h>
#include <cuda_fp16.h>
#include <cstdint>
#include <math.h>

#define BB   2
#define SS   2048
#define HH   2304
#define NH   8
#define HD   256
#define NKV  4
#define WIN  512
#define MROWS (BB*SS)            // 4096
#define KO   2048
#define NQKV (NH*HD + 2*NKV*HD)  // 4096
#define NST   3
#define STAGE_BYTES 32768
#define GEMM_SMEM (NST*STAGE_BYTES + 1024)
#define ATT_SMEM (3*32768 + 1024)

// ------------------------- device scratch (no allocs allowed) ---------------
__device__ float g_q[(size_t)BB*NH*SS*HD];
__device__ float g_k[(size_t)BB*NKV*SS*HD];
__device__ float g_cos[(size_t)BB*SS*128];
__device__ float g_sin[(size_t)BB*SS*128];
__device__ __align__(256) __half g_a2 [(size_t)MROWS*HH];
__device__ __align__(256) __half g_b2 [(size_t)NQKV*HH];
__device__ __align__(256) __half g_a2o[(size_t)MROWS*KO];
__device__ __align__(256) __half g_b2o[(size_t)HH*KO];
__device__ __align__(256) __half g_qh[(size_t)BB*NH*SS*HD];
__device__ __align__(256) __half g_kh[(size_t)BB*NKV*SS*HD];
__device__ __align__(256) __half g_vh[(size_t)BB*NKV*SS*HD];

// ------------------------- PTX helpers --------------------------------------
__device__ __forceinline__ uint32_t smem_u32(const void* p) {
    uint32_t a;
    asm("{ .reg .u64 t; cvta.to.shared.u64 t, %1; cvt.u32.u64 %0, t; }" : "=r"(a) : "l"(p));
    return a;
}
__device__ __forceinline__ uint32_t h2u(__half2 v) {
    return *reinterpret_cast<uint32_t*>(&v);
}
__device__ __forceinline__ void cp_async16(uint32_t saddr, const void* gaddr) {
    asm volatile("cp.async.cg.shared.global [%0], [%1], 16;" :: "r"(saddr), "l"(gaddr) : "memory");
}
__device__ __forceinline__ void cp_commit() {
    asm volatile("cp.async.commit_group;" ::: "memory");
}
__device__ __forceinline__ void cp_wait_1() {
    asm volatile("cp.async.wait_group 1;" ::: "memory");
}
__device__ __forceinline__ void ldsm4(uint32_t* r, uint32_t addr) {
    asm volatile("ldmatrix.sync.aligned.m8n8.x4.shared.b16 {%0,%1,%2,%3}, [%4];"
                 : "=r"(r[0]), "=r"(r[1]), "=r"(r[2]), "=r"(r[3]) : "r"(addr));
}
__device__ __forceinline__ void ldsm4t(uint32_t* r, uint32_t addr) {
    asm volatile("ldmatrix.sync.aligned.m8n8.x4.trans.shared.b16 {%0,%1,%2,%3}, [%4];"
                 : "=r"(r[0]), "=r"(r[1]), "=r"(r[2]), "=r"(r[3]) : "r"(addr));
}
__device__ __forceinline__ void mma16816h(float* c, const uint32_t* a, uint32_t b0, uint32_t b1) {
    asm volatile(
        "mma.sync.aligned.m16n8k16.row.col.f32.f16.f16.f32 "
        "{%0,%1,%2,%3}, {%4,%5,%6,%7}, {%8,%9}, {%0,%1,%2,%3};"
        : "+f"(c[0]), "+f"(c[1]), "+f"(c[2]), "+f"(c[3])
        : "r"(a[0]), "r"(a[1]), "r"(a[2]), "r"(a[3]), "r"(b0), "r"(b1));
}
#define SWZ(off) ((off) ^ (((off) >> 3) & 0x70))

__device__ __forceinline__ uint32_t tile_off(int row, int d) {
    uint32_t off = (uint32_t)(row * 128 + (d & 63) * 2);
    return (uint32_t)((d >> 6) * 8192) + SWZ(off);
}

// ------------------------- prep kernels -------------------------------------
__global__ __launch_bounds__(256) void conv_half4(
    const float* __restrict__ X, __half* __restrict__ Y, int n4)
{
    int t = blockIdx.x * blockDim.x + threadIdx.x;
    if (t >= n4) return;
    float4 v = ((const float4*)X)[t];
    __half2* y = (__half2*)Y + 2 * t;
    y[0] = __floats2half2_rn(v.x, v.y);
    y[1] = __floats2half2_rn(v.z, v.w);
}
__global__ __launch_bounds__(256) void transp_h(
    const float* __restrict__ W, __half* __restrict__ Y, int K, int N)
{
    __shared__ float t[32][33];
    int k0 = blockIdx.y * 32, n0 = blockIdx.x * 32;
    int tx = threadIdx.x & 31, ty = threadIdx.x >> 5;
#pragma unroll
    for (int i = 0; i < 4; i++)
        t[ty + i * 8][tx] = W[(size_t)(k0 + ty + i * 8) * N + n0 + tx];
    __syncthreads();
#pragma unroll
    for (int i = 0; i < 4; i++) {
        int n = n0 + ty + i * 8;
        int k = k0 + tx;
        Y[(size_t)n * K + k] = __float2half(t[tx][ty + i * 8]);
    }
}
__global__ __launch_bounds__(256) void transp_qkv(
    const float* __restrict__ Wq, const float* __restrict__ Wk,
    const float* __restrict__ Wv, __half* __restrict__ Y)
{
    __shared__ float t[32][33];
    int bx = blockIdx.x;
    const float* W; int n0; size_t nbase; int N;
    if (bx < 64)       { W = Wq; n0 = bx * 32;         nbase = 0;    N = 2048; }
    else if (bx < 96)  { W = Wk; n0 = (bx - 64) * 32;  nbase = 2048; N = 1024; }
    else               { W = Wv; n0 = (bx - 96) * 32;  nbase = 3072; N = 1024; }
    int k0 = blockIdx.y * 32;
    int tx = threadIdx.x & 31, ty = threadIdx.x >> 5;
#pragma unroll
    for (int i = 0; i < 4; i++)
        t[ty + i * 8][tx] = W[(size_t)(k0 + ty + i * 8) * N + n0 + tx];
    __syncthreads();
#pragma unroll
    for (int i = 0; i < 4; i++) {
        size_t n = nbase + n0 + ty + i * 8;
        int k = k0 + tx;
        Y[n * HH + k] = __float2half(t[tx][ty + i * 8]);
    }
}

// ------------------------- HMMA GEMM (fp16 operands) ------------------------
__global__ __launch_bounds__(256, 2) void gemm_tc(
    const __half* __restrict__ A2, const __half* __restrict__ B2,
    float* __restrict__ Cq, float* __restrict__ Ck, __half* __restrict__ Cv,
    int K2, int mode, int ldN)
{
    extern __shared__ char dsm[];
    const int tid = threadIdx.x;
    const int wid = tid >> 5;
    const int lane = tid & 31;
    const int m0 = blockIdx.y * 128;
    const int n0 = blockIdx.x * 128;
    const int warpM = (wid & 3) * 32;
    const int warpN = (wid >> 2) * 64;

    uint32_t raw = smem_u32(dsm);
    uint32_t sbase = (raw + 1023u) & ~1023u;
    char* dtile = dsm + (sbase - raw);

    const int nk = K2 >> 6;
    const int colb = (tid & 7) * 16;
    const int r0 = tid >> 3;

    float c[2][8][4];
#pragma unroll
    for (int mi = 0; mi < 2; mi++)
#pragma unroll
        for (int nf = 0; nf < 8; nf++)
#pragma unroll
            for (int j = 0; j < 4; j++) c[mi][nf][j] = 0.f;

    const int lrow = lane & 15;
    const int lchunk = (lane >> 4) * 16;

#pragma unroll
    for (int s = 0; s < NST - 1; s++) {
        uint32_t sA = sbase + s * STAGE_BYTES;
        uint32_t sB = sA + 16384;
        int k0 = s * 64;
#pragma unroll
        for (int i = 0; i < 4; i++) {
            int row = i * 32 + r0;
            uint32_t so = SWZ((uint32_t)(row * 128 + colb));
            cp_async16(sA + so, A2 + (size_t)(m0 + row) * K2 + k0 + (tid & 7) * 8);
            cp_async16(sB + so, B2 + (size_t)(n0 + row) * K2 + k0 + (tid & 7) * 8);
        }
        cp_commit();
    }

    for (int ck = 0; ck < nk; ck++) {
        const int s = ck - (ck / NST) * NST;
        cp_wait_1();
        __syncthreads();

        const int nck = ck + NST - 1;
        if (nck < nk) {
            const int ps = nck - (nck / NST) * NST;
            uint32_t pA = sbase + ps * STAGE_BYTES;
            uint32_t pB = pA + 16384;
            int k0 = nck * 64;
#pragma unroll
            for (int i = 0; i < 4; i++) {
                int row = i * 32 + r0;
                uint32_t so = SWZ((uint32_t)(row * 128 + colb));
                cp_async16(pA + so, A2 + (size_t)(m0 + row) * K2 + k0 + (tid & 7) * 8);
                cp_async16(pB + so, B2 + (size_t)(n0 + row) * K2 + k0 + (tid & 7) * 8);
            }
        }
        cp_commit();

        uint32_t sA = sbase + s * STAGE_BYTES;
        uint32_t sB = sA + 16384;
#pragma unroll
        for (int ks = 0; ks < 4; ks++) {
            const int kb = ks * 32 + lchunk;
            uint32_t a[2][4], b[4][4];
#pragma unroll
            for (int mi = 0; mi < 2; mi++) {
                int row = warpM + mi * 16 + lrow;
                ldsm4(a[mi], sA + SWZ((uint32_t)(row * 128 + kb)));
            }
#pragma unroll
            for (int ni = 0; ni < 4; ni++) {
                int row = warpN + ni * 16 + lrow;
                ldsm4(b[ni], sB + SWZ((uint32_t)(row * 128 + kb)));
            }
#pragma unroll
            for (int mi = 0; mi < 2; mi++)
#pragma unroll
                for (int ni = 0; ni < 4; ni++) {
                    mma16816h(c[mi][2 * ni + 0], a[mi], b[ni][0], b[ni][2]);
                    mma16816h(c[mi][2 * ni + 1], a[mi], b[ni][1], b[ni][3]);
                }
        }
    }

    __syncthreads();
    float* stile = (float*)dtile;
    {
        int rquad = lane >> 2;
        int cpair = (lane & 3) << 1;
#pragma unroll
        for (int mi = 0; mi < 2; mi++) {
            int rbase = warpM + mi * 16 + rquad;
#pragma unroll
            for (int nf = 0; nf < 8; nf++) {
                int col = warpN + nf * 8 + cpair;
                *(float2*)&stile[rbase * 132 + col]       = make_float2(c[mi][nf][0], c[mi][nf][1]);
                *(float2*)&stile[(rbase + 8) * 132 + col] = make_float2(c[mi][nf][2], c[mi][nf][3]);
            }
        }
    }
    __syncthreads();

    if (mode == 0) {
#pragma unroll
        for (int i = 0; i < 16; i++) {
            int idx = i * 256 + tid;
            int row = idx >> 5, c4 = idx & 31;
            float4 v = *(float4*)&stile[row * 132 + c4 * 4];
            int m = m0 + row;
            *(float4*)&Cq[(size_t)m * ldN + n0 + c4 * 4] = v;
        }
    } else if (n0 < 3072) {
        float* tens; int hh, hp;
        if (n0 < 2048) { tens = Cq; hh = n0 >> 8;          hp = NH; }
        else           { tens = Ck; hh = (n0 - 2048) >> 8; hp = NKV; }
        int d0 = n0 & 255;
#pragma unroll
        for (int i = 0; i < 16; i++) {
            int idx = i * 256 + tid;
            int row = idx >> 5, c4 = idx & 31;
            float4 v = *(float4*)&stile[row * 132 + c4 * 4];
            int m = m0 + row;
            int b = m >> 11, sq = m & (SS - 1);
            *(float4*)&tens[(((size_t)(b * hp + hh)) * SS + sq) * HD + d0 + c4 * 4] = v;
        }
    } else {
        int hh = (n0 - 3072) >> 8;
        int d0 = n0 & 255;
#pragma unroll
        for (int i = 0; i < 16; i++) {
            int idx = i * 256 + tid;
            int row = idx >> 5, c4 = idx & 31;
            float4 v = *(float4*)&stile[row * 132 + c4 * 4];
            int m = m0 + row;
            int b = m >> 11, sq = m & (SS - 1);
            __half* dst = Cv + (((size_t)(b * NKV + hh)) * SS + sq) * HD + d0 + c4 * 4;
            *(__half2*)&dst[0] = __floats2half2_rn(v.x, v.y);
            *(__half2*)&dst[2] = __floats2half2_rn(v.z, v.w);
        }
    }
}

// --------------- trig table + table-lookup RoPE ------------------------------
#define NEG_L2F (-0.1038095500548783f)
__global__ __launch_bounds__(256) void trig_table(
    const int* __restrict__ pos_ids, float* __restrict__ Ct, float* __restrict__ St)
{
    int t = blockIdx.x * blockDim.x + threadIdx.x;   // over BB*SS*128
    if (t >= BB * SS * 128) return;
    int d = t & 127;
    int s = (t >> 7) & (SS - 1);
    int b = t >> 18;
    float p = (float)pos_ids[b * SS + s];
    float ang = p * exp2f((float)d * NEG_L2F);
    float si, co;
    sincosf(ang, &si, &co);
    Ct[t] = co;
    St[t] = si;
}

#define QROPE_N (BB*NH*SS*128)
#define KROPE_N (BB*NKV*SS*128)
__global__ __launch_bounds__(256) void rope_fused(
    const float* __restrict__ Q, __half* __restrict__ Qh,
    const float* __restrict__ K, __half* __restrict__ Kh,
    const float* __restrict__ Ct, const float* __restrict__ St, float qscale)
{
    int t = blockIdx.x * blockDim.x + threadIdx.x;
    const float* X; __half* Y; int heads; float scale;
    if (t < QROPE_N) { X = Q; Y = Qh; heads = NH; scale = qscale; }
    else { t -= QROPE_N; if (t >= KROPE_N) return; X = K; Y = Kh; heads = NKV; scale = 1.f; }
    int d = t & 127;
    int s = (t >> 7) & (SS - 1);
    int rest = t >> 18;
    int hh = rest % heads;
    int b  = rest / heads;
    int ti = (b << 18) + (s << 7) + d;
    float co = __ldg(&Ct[ti]);
    float si = __ldg(&St[ti]);
    size_t base = (((size_t)b * heads + hh) * SS + s) * HD;
    float x1 = X[base + d], x2 = X[base + d + 128];
    Y[base + d]       = __float2half((x1 * co - x2 * si) * scale);
    Y[base + d + 128] = __float2half((x2 * co + x1 * si) * scale);
}

// ------------------------- tensor-core flash attention ----------------------
__device__ __forceinline__ void cp_att_wait1() {
    asm volatile("cp.async.wait_group 1;" ::: "memory");
}
__device__ __forceinline__ void load_tile_async(uint32_t sdst, const __half* g, int tid) {
#pragma unroll
    for (int i = 0; i < 16; i++) {
        int idx = i * 128 + tid;
        int row = idx >> 5;
        int d = (idx & 31) * 8;
        cp_async16(sdst + tile_off(row, d), g + row * HD + d);
    }
}

__global__ __launch_bounds__(128, 2) void attn_tc(
    const __half* __restrict__ Qh,
    const __half* __restrict__ Kh, const __half* __restrict__ Vh,
    __half* __restrict__ A2O)
{
    extern __shared__ char dsm[];
    uint32_t raw = smem_u32(dsm);
    uint32_t sb = (raw + 1023u) & ~1023u;
    const uint32_t sQh = sb, sKh = sb + 32768, sVh = sb + 65536;

    const int tid = threadIdx.x;
    const int wid = tid >> 5;
    const int lane = tid & 31;
    const int qblk = blockIdx.x;
    const int h = blockIdx.y;
    const int b = blockIdx.z;
    const int kv = h >> 1;
    const int warpM = wid * 16;

    const __half* qhp = Qh + (((size_t)(b * NH + h)) * SS + qblk * 64) * HD;
    const __half* khp = Kh + ((size_t)(b * NKV + kv)) * SS * HD;
    const __half* vhp = Vh + ((size_t)(b * NKV + kv)) * SS * HD;

    int lo = qblk * 64 - (WIN - 1);
    if (lo < 0) lo = 0;
    lo &= ~63;
    const int hi = qblk * 64;

    load_tile_async(sQh, qhp, tid);
    load_tile_async(sKh, khp + (size_t)lo * HD, tid);
    cp_commit();
    load_tile_async(sVh, vhp + (size_t)lo * HD, tid);
    cp_commit();

    float oacc[32][4];
#pragma unroll
    for (int i = 0; i < 32; i++)
#pragma unroll
        for (int j = 0; j < 4; j++) oacc[i][j] = 0.f;
    float m0 = -1e30f, m1 = -1e30f, l0 = 0.f, l1 = 0.f;

    const int lrow = lane & 15;
    const int lhalf = (lane >> 4) * 16;
    const int qi = qblk * 64 + warpM + (lane >> 2);

    for (int kt = lo; kt <= hi; kt += 64) {
        cp_att_wait1();
        __syncthreads();

        float sacc[8][4];
#pragma unroll
        for (int i = 0; i < 8; i++)
#pragma unroll
            for (int j = 0; j < 4; j++) sacc[i][j] = 0.f;

#pragma unroll
        for (int kc = 0; kc < 16; kc++) {
            const int c = kc >> 2;
            const int colb = (kc & 3) * 32 + lhalf;
            uint32_t aqh[4];
            uint32_t aoff = (uint32_t)(c * 8192) + SWZ((uint32_t)((warpM + lrow) * 128 + colb));
            ldsm4(aqh, sQh + aoff);
#pragma unroll
            for (int g = 0; g < 4; g++) {
                uint32_t boff = (uint32_t)(c * 8192) + SWZ((uint32_t)((g * 16 + lrow) * 128 + colb));
                uint32_t bh[4];
                ldsm4(bh, sKh + boff);
                mma16816h(sacc[2 * g],     aqh, bh[0], bh[2]);
                mma16816h(sacc[2 * g + 1], aqh, bh[1], bh[3]);
            }
        }
        __syncthreads();
        if (kt + 64 <= hi)
            load_tile_async(sKh, khp + (size_t)(kt + 64) * HD, tid);
        cp_commit();

        float tm0 = -1e30f, tm1 = -1e30f;
#pragma unroll
        for (int nt = 0; nt < 8; nt++) {
#pragma unroll
            for (int j = 0; j < 4; j++) {
                int kj = kt + nt * 8 + (lane & 3) * 2 + (j & 1);
                int row = qi + ((j >> 1) * 8);
                float x = sacc[nt][j];
                float e = __expf(2.f * x);
                float s = 50.f * __fdividef(e - 1.f, e + 1.f);
                bool ok = (kj <= row) && (row - kj < WIN);
                s = ok ? s : -1e30f;
                sacc[nt][j] = s;
                if (j < 2) tm0 = fmaxf(tm0, s); else tm1 = fmaxf(tm1, s);
            }
        }
        tm0 = fmaxf(tm0, __shfl_xor_sync(0xffffffffu, tm0, 1));
        tm0 = fmaxf(tm0, __shfl_xor_sync(0xffffffffu, tm0, 2));
        tm1 = fmaxf(tm1, __shfl_xor_sync(0xffffffffu, tm1, 1));
        tm1 = fmaxf(tm1, __shfl_xor_sync(0xffffffffu, tm1, 2));

        float mn0 = fmaxf(m0, tm0), mn1 = fmaxf(m1, tm1);
        float al0 = __expf(m0 - mn0), al1 = __expf(m1 - mn1);
        m0 = mn0; m1 = mn1;

        float rs0 = 0.f, rs1 = 0.f;
#pragma unroll
        for (int nt = 0; nt < 8; nt++) {
            float p0 = __expf(sacc[nt][0] - mn0);
            float p1 = __expf(sacc[nt][1] - mn0);
            float p2 = __expf(sacc[nt][2] - mn1);
            float p3 = __expf(sacc[nt][3] - mn1);
            sacc[nt][0] = p0; sacc[nt][1] = p1; sacc[nt][2] = p2; sacc[nt][3] = p3;
            rs0 += p0 + p1; rs1 += p2 + p3;
        }
        rs0 += __shfl_xor_sync(0xffffffffu, rs0, 1);
        rs0 += __shfl_xor_sync(0xffffffffu, rs0, 2);
        rs1 += __shfl_xor_sync(0xffffffffu, rs1, 1);
        rs1 += __shfl_xor_sync(0xffffffffu, rs1, 2);
        l0 = l0 * al0 + rs0;
        l1 = l1 * al1 + rs1;

        uint32_t aP[4][4];
#pragma unroll
        for (int kc2 = 0; kc2 < 4; kc2++) {
            aP[kc2][0] = h2u(__floats2half2_rn(sacc[2 * kc2][0],     sacc[2 * kc2][1]));
            aP[kc2][1] = h2u(__floats2half2_rn(sacc[2 * kc2][2],     sacc[2 * kc2][3]));
            aP[kc2][2] = h2u(__floats2half2_rn(sacc[2 * kc2 + 1][0], sacc[2 * kc2 + 1][1]));
            aP[kc2][3] = h2u(__floats2half2_rn(sacc[2 * kc2 + 1][2], sacc[2 * kc2 + 1][3]));
        }

#pragma unroll
        for (int dt = 0; dt < 32; dt++) {
            oacc[dt][0] *= al0; oacc[dt][1] *= al0;
            oacc[dt][2] *= al1; oacc[dt][3] *= al1;
        }

        cp_att_wait1();
        __syncthreads();

#pragma unroll
        for (int kc2 = 0; kc2 < 4; kc2++) {
#pragma unroll
            for (int dg = 0; dg < 16; dg++) {
                int key = kc2 * 16 + lrow;
                int d = dg * 16 + (lane >> 4) * 8;
                uint32_t r[4];
                ldsm4t(r, sVh + tile_off(key, d));
                mma16816h(oacc[dg * 2],     aP[kc2], r[0], r[1]);
                mma16816h(oacc[dg * 2 + 1], aP[kc2], r[2], r[3]);
            }
        }
        __syncthreads();
        if (kt + 64 <= hi)
            load_tile_async(sVh, vhp + (size_t)(kt + 64) * HD, tid);
        cp_commit();
    }

    float il0 = __fdividef(1.f, l0);
    float il1 = __fdividef(1.f, l1);
    __half* a0 = A2O + ((size_t)(b * SS + qi)) * KO + h * HD;
    __half* a1 = A2O + ((size_t)(b * SS + qi + 8)) * KO + h * HD;
    int cbase = (lane & 3) * 2;
#pragma unroll
    for (int dt = 0; dt < 32; dt++) {
        int col = dt * 8 + cbase;
        *(__half2*)&a0[col] = __floats2half2_rn(oacc[dt][0] * il0, oacc[dt][1] * il0);
        *(__half2*)&a1[col] = __floats2half2_rn(oacc[dt][2] * il1, oacc[dt][3] * il1);
    }
}

// ---------------------------------------------------------------------------
extern "C" void kernel_launch(void* const* d_in, const int* in_sizes, int n_in,
                              void* d_out, int out_size)
{
    const float* hid = (const float*)d_in[0];
    const int*   pos = (const int*)d_in[2];
    const float* Wq  = (const float*)d_in[3];
    const float* Wk  = (const float*)d_in[4];
    const float* Wv  = (const float*)d_in[5];
    const float* Wo  = (const float*)d_in[6];
    float* out = (float*)d_out;

    float *qp, *kp, *ct, *st;
    __half *a2, *b2, *a2o, *b2o, *qh_, *kh_, *vh_;
    cudaGetSymbolAddress((void**)&qp,  g_q);
    cudaGetSymbolAddress((void**)&kp,  g_k);
    cudaGetSymbolAddress((void**)&ct,  g_cos);
    cudaGetSymbolAddress((void**)&st,  g_sin);
    cudaGetSymbolAddress((void**)&a2,  g_a2);
    cudaGetSymbolAddress((void**)&b2,  g_b2);
    cudaGetSymbolAddress((void**)&a2o, g_a2o);
    cudaGetSymbolAddress((void**)&b2o, g_b2o);
    cudaGetSymbolAddress((void**)&qh_, g_qh);
    cudaGetSymbolAddress((void**)&kh_, g_kh);
    cudaGetSymbolAddress((void**)&vh_, g_vh);

    cudaFuncSetAttribute(gemm_tc, cudaFuncAttributeMaxDynamicSharedMemorySize, GEMM_SMEM);
    cudaFuncSetAttribute(attn_tc, cudaFuncAttributeMaxDynamicSharedMemorySize, ATT_SMEM);

    // ---- single stream; fused prep kernels ----
    conv_half4<<<(MROWS*HH/4 + 255)/256, 256>>>(hid, a2, MROWS*HH/4);
    transp_qkv<<<dim3(128, HH/32), 256>>>(Wq, Wk, Wv, b2);
    trig_table<<<(BB*SS*128 + 255)/256, 256>>>(pos, ct, st);

    gemm_tc<<<dim3(NQKV/128, MROWS/128), 256, GEMM_SMEM>>>(a2, b2, qp, kp, vh_, HH, 1, 0);

    rope_fused<<<(QROPE_N + KROPE_N + 255)/256, 256>>>(qp, qh_, kp, kh_, ct, st, 1.f/(16.f*50.f));

    attn_tc<<<dim3(SS/64, NH, BB), 128, ATT_SMEM>>>(qh_, kh_, vh_, a2o);

    transp_h<<<dim3(HH/32, 2048/32), 256>>>(Wo, b2o, 2048, HH);
    gemm_tc<<<dim3(HH/128, MROWS/128), 256, GEMM_SMEM>>>(a2o, b2o, out, nullptr, nullptr, KO, 0, HH);
}

// round 16
// speedup vs baseline: 1.1242x; 1.1242x over previous
#include <cuda_runtime.h>
#include <cuda_fp16.h>
#include <cstdint>
#include <math.h>

#define BB   2
#define SS   2048
#define HH   2304
#define NH   8
#define HD   256
#define NKV  4
#define WIN  512
#define MROWS (BB*SS)            // 4096
#define KO   2048
#define NQKV (NH*HD + 2*NKV*HD)  // 4096
#define NST   3
#define STAGE_BYTES 32768
#define GEMM_SMEM (NST*STAGE_BYTES + 1024)
#define ATT_SMEM (3*32768 + 1024)

// ------------------------- device scratch (no allocs allowed) ---------------
__device__ float g_q[(size_t)BB*NH*SS*HD];
__device__ float g_k[(size_t)BB*NKV*SS*HD];
__device__ __align__(256) __half g_a2 [(size_t)MROWS*HH];
__device__ __align__(256) __half g_b2 [(size_t)NQKV*HH];
__device__ __align__(256) __half g_a2o[(size_t)MROWS*KO];
__device__ __align__(256) __half g_b2o[(size_t)HH*KO];
__device__ __align__(256) __half g_qh[(size_t)BB*NH*SS*HD];
__device__ __align__(256) __half g_kh[(size_t)BB*NKV*SS*HD];
__device__ __align__(256) __half g_vh[(size_t)BB*NKV*SS*HD];

// ------------------------- PTX helpers --------------------------------------
__device__ __forceinline__ uint32_t smem_u32(const void* p) {
    uint32_t a;
    asm("{ .reg .u64 t; cvta.to.shared.u64 t, %1; cvt.u32.u64 %0, t; }" : "=r"(a) : "l"(p));
    return a;
}
__device__ __forceinline__ uint32_t h2u(__half2 v) {
    return *reinterpret_cast<uint32_t*>(&v);
}
__device__ __forceinline__ void cp_async16(uint32_t saddr, const void* gaddr) {
    asm volatile("cp.async.cg.shared.global [%0], [%1], 16;" :: "r"(saddr), "l"(gaddr) : "memory");
}
__device__ __forceinline__ void cp_commit() {
    asm volatile("cp.async.commit_group;" ::: "memory");
}
__device__ __forceinline__ void cp_wait_1() {
    asm volatile("cp.async.wait_group 1;" ::: "memory");
}
__device__ __forceinline__ void ldsm4(uint32_t* r, uint32_t addr) {
    asm volatile("ldmatrix.sync.aligned.m8n8.x4.shared.b16 {%0,%1,%2,%3}, [%4];"
                 : "=r"(r[0]), "=r"(r[1]), "=r"(r[2]), "=r"(r[3]) : "r"(addr));
}
__device__ __forceinline__ void ldsm4t(uint32_t* r, uint32_t addr) {
    asm volatile("ldmatrix.sync.aligned.m8n8.x4.trans.shared.b16 {%0,%1,%2,%3}, [%4];"
                 : "=r"(r[0]), "=r"(r[1]), "=r"(r[2]), "=r"(r[3]) : "r"(addr));
}
__device__ __forceinline__ void mma16816h(float* c, const uint32_t* a, uint32_t b0, uint32_t b1) {
    asm volatile(
        "mma.sync.aligned.m16n8k16.row.col.f32.f16.f16.f32 "
        "{%0,%1,%2,%3}, {%4,%5,%6,%7}, {%8,%9}, {%0,%1,%2,%3};"
        : "+f"(c[0]), "+f"(c[1]), "+f"(c[2]), "+f"(c[3])
        : "r"(a[0]), "r"(a[1]), "r"(a[2]), "r"(a[3]), "r"(b0), "r"(b1));
}
#define SWZ(off) ((off) ^ (((off) >> 3) & 0x70))

__device__ __forceinline__ uint32_t tile_off(int row, int d) {
    uint32_t off = (uint32_t)(row * 128 + (d & 63) * 2);
    return (uint32_t)((d >> 6) * 8192) + SWZ(off);
}

// ------------------------- prep kernels -------------------------------------
__global__ __launch_bounds__(256) void conv_half4(
    const float* __restrict__ X, __half* __restrict__ Y, int n4)
{
    int t = blockIdx.x * blockDim.x + threadIdx.x;
    if (t >= n4) return;
    float4 v = ((const float4*)X)[t];
    __half2* y = (__half2*)Y + 2 * t;
    y[0] = __floats2half2_rn(v.x, v.y);
    y[1] = __floats2half2_rn(v.z, v.w);
}
__global__ __launch_bounds__(256) void transp_h(
    const float* __restrict__ W, __half* __restrict__ Y, int K, int N)
{
    __shared__ float t[32][33];
    int k0 = blockIdx.y * 32, n0 = blockIdx.x * 32;
    int tx = threadIdx.x & 31, ty = threadIdx.x >> 5;
#pragma unroll
    for (int i = 0; i < 4; i++)
        t[ty + i * 8][tx] = W[(size_t)(k0 + ty + i * 8) * N + n0 + tx];
    __syncthreads();
#pragma unroll
    for (int i = 0; i < 4; i++) {
        int n = n0 + ty + i * 8;
        int k = k0 + tx;
        Y[(size_t)n * K + k] = __float2half(t[tx][ty + i * 8]);
    }
}
__global__ __launch_bounds__(256) void transp_qkv(
    const float* __restrict__ Wq, const float* __restrict__ Wk,
    const float* __restrict__ Wv, __half* __restrict__ Y)
{
    __shared__ float t[32][33];
    int bx = blockIdx.x;
    const float* W; int n0; size_t nbase; int N;
    if (bx < 64)       { W = Wq; n0 = bx * 32;         nbase = 0;    N = 2048; }
    else if (bx < 96)  { W = Wk; n0 = (bx - 64) * 32;  nbase = 2048; N = 1024; }
    else               { W = Wv; n0 = (bx - 96) * 32;  nbase = 3072; N = 1024; }
    int k0 = blockIdx.y * 32;
    int tx = threadIdx.x & 31, ty = threadIdx.x >> 5;
#pragma unroll
    for (int i = 0; i < 4; i++)
        t[ty + i * 8][tx] = W[(size_t)(k0 + ty + i * 8) * N + n0 + tx];
    __syncthreads();
#pragma unroll
    for (int i = 0; i < 4; i++) {
        size_t n = nbase + n0 + ty + i * 8;
        int k = k0 + tx;
        Y[n * HH + k] = __float2half(t[tx][ty + i * 8]);
    }
}

// ------------------------- HMMA GEMM (fp16 operands) ------------------------
// Single-sync multistage; strength-reduced addressing (no per-iter div/imul).
__global__ __launch_bounds__(256, 2) void gemm_tc(
    const __half* __restrict__ A2, const __half* __restrict__ B2,
    float* __restrict__ Cq, float* __restrict__ Ck, __half* __restrict__ Cv,
    int K2, int mode, int ldN)
{
    extern __shared__ char dsm[];
    const int tid = threadIdx.x;
    const int wid = tid >> 5;
    const int lane = tid & 31;
    const int m0 = blockIdx.y * 128;
    const int n0 = blockIdx.x * 128;
    const int warpM = (wid & 3) * 32;
    const int warpN = (wid >> 2) * 64;

    uint32_t raw = smem_u32(dsm);
    uint32_t sbase = (raw + 1023u) & ~1023u;
    char* dtile = dsm + (sbase - raw);

    const int nk = K2 >> 6;
    const int colb = (tid & 7) * 16;
    const int r0 = tid >> 3;

    float c[2][8][4];
#pragma unroll
    for (int mi = 0; mi < 2; mi++)
#pragma unroll
        for (int nf = 0; nf < 8; nf++)
#pragma unroll
            for (int j = 0; j < 4; j++) c[mi][nf][j] = 0.f;

    const int lrow = lane & 15;
    const int lchunk = (lane >> 4) * 16;

    // persistent global pointers + loop-invariant swizzled smem offsets
    const __half* pA[4];
    const __half* pB[4];
    uint32_t so[4];
#pragma unroll
    for (int i = 0; i < 4; i++) {
        int row = i * 32 + r0;
        pA[i] = A2 + (size_t)(m0 + row) * K2 + (tid & 7) * 8;
        pB[i] = B2 + (size_t)(n0 + row) * K2 + (tid & 7) * 8;
        so[i] = SWZ((uint32_t)(row * 128 + colb));
    }

    // prologue: fill stages 0..NST-2 with chunks 0..NST-2
#pragma unroll
    for (int s = 0; s < NST - 1; s++) {
        uint32_t sA = sbase + s * STAGE_BYTES;
        uint32_t sB = sA + 16384;
#pragma unroll
        for (int i = 0; i < 4; i++) {
            cp_async16(sA + so[i], pA[i] + s * 64);
            cp_async16(sB + so[i], pB[i] + s * 64);
        }
        cp_commit();
    }
#pragma unroll
    for (int i = 0; i < 4; i++) { pA[i] += (NST - 1) * 64; pB[i] += (NST - 1) * 64; }

    int s = 0;            // compute stage
    int ps = NST - 1;     // prefetch stage
    int remain = nk - (NST - 1);   // prefetches remaining
    for (int ck = 0; ck < nk; ck++) {
        cp_wait_1();
        __syncthreads();

        if (remain > 0) {
            uint32_t psA = sbase + ps * STAGE_BYTES;
            uint32_t psB = psA + 16384;
#pragma unroll
            for (int i = 0; i < 4; i++) {
                cp_async16(psA + so[i], pA[i]);
                cp_async16(psB + so[i], pB[i]);
                pA[i] += 64; pB[i] += 64;
            }
            remain--;
        }
        cp_commit();

        uint32_t sA = sbase + s * STAGE_BYTES;
        uint32_t sB = sA + 16384;
#pragma unroll
        for (int ks = 0; ks < 4; ks++) {
            const int kb = ks * 32 + lchunk;
            uint32_t a[2][4], b[4][4];
#pragma unroll
            for (int mi = 0; mi < 2; mi++) {
                int row = warpM + mi * 16 + lrow;
                ldsm4(a[mi], sA + SWZ((uint32_t)(row * 128 + kb)));
            }
#pragma unroll
            for (int ni = 0; ni < 4; ni++) {
                int row = warpN + ni * 16 + lrow;
                ldsm4(b[ni], sB + SWZ((uint32_t)(row * 128 + kb)));
            }
#pragma unroll
            for (int mi = 0; mi < 2; mi++)
#pragma unroll
                for (int ni = 0; ni < 4; ni++) {
                    mma16816h(c[mi][2 * ni + 0], a[mi], b[ni][0], b[ni][2]);
                    mma16816h(c[mi][2 * ni + 1], a[mi], b[ni][1], b[ni][3]);
                }
        }
        if (++s == NST) s = 0;
        if (++ps == NST) ps = 0;
    }

    __syncthreads();
    float* stile = (float*)dtile;
    {
        int rquad = lane >> 2;
        int cpair = (lane & 3) << 1;
#pragma unroll
        for (int mi = 0; mi < 2; mi++) {
            int rbase = warpM + mi * 16 + rquad;
#pragma unroll
            for (int nf = 0; nf < 8; nf++) {
                int col = warpN + nf * 8 + cpair;
                *(float2*)&stile[rbase * 132 + col]       = make_float2(c[mi][nf][0], c[mi][nf][1]);
                *(float2*)&stile[(rbase + 8) * 132 + col] = make_float2(c[mi][nf][2], c[mi][nf][3]);
            }
        }
    }
    __syncthreads();

    if (mode == 0) {
#pragma unroll
        for (int i = 0; i < 16; i++) {
            int idx = i * 256 + tid;
            int row = idx >> 5, c4 = idx & 31;
            float4 v = *(float4*)&stile[row * 132 + c4 * 4];
            int m = m0 + row;
            *(float4*)&Cq[(size_t)m * ldN + n0 + c4 * 4] = v;
        }
    } else if (n0 < 3072) {
        float* tens; int hh, hp;
        if (n0 < 2048) { tens = Cq; hh = n0 >> 8;          hp = NH; }
        else           { tens = Ck; hh = (n0 - 2048) >> 8; hp = NKV; }
        int d0 = n0 & 255;
#pragma unroll
        for (int i = 0; i < 16; i++) {
            int idx = i * 256 + tid;
            int row = idx >> 5, c4 = idx & 31;
            float4 v = *(float4*)&stile[row * 132 + c4 * 4];
            int m = m0 + row;
            int b = m >> 11, sq = m & (SS - 1);
            *(float4*)&tens[(((size_t)(b * hp + hh)) * SS + sq) * HD + d0 + c4 * 4] = v;
        }
    } else {
        int hh = (n0 - 3072) >> 8;
        int d0 = n0 & 255;
#pragma unroll
        for (int i = 0; i < 16; i++) {
            int idx = i * 256 + tid;
            int row = idx >> 5, c4 = idx & 31;
            float4 v = *(float4*)&stile[row * 132 + c4 * 4];
            int m = m0 + row;
            int b = m >> 11, sq = m & (SS - 1);
            __half* dst = Cv + (((size_t)(b * NKV + hh)) * SS + sq) * HD + d0 + c4 * 4;
            *(__half2*)&dst[0] = __floats2half2_rn(v.x, v.y);
            *(__half2*)&dst[2] = __floats2half2_rn(v.z, v.w);
        }
    }
}

// --------------- fused RoPE (q + k in one launch, exp2f freq) ----------------
#define QROPE_N (BB*NH*SS*128)
#define KROPE_N (BB*NKV*SS*128)
#define NEG_L2F (-0.1038095500548783f)
__global__ __launch_bounds__(256) void rope_fused(
    const float* __restrict__ Q, __half* __restrict__ Qh,
    const float* __restrict__ K, __half* __restrict__ Kh,
    const int* __restrict__ pos_ids, float qscale)
{
    int t = blockIdx.x * blockDim.x + threadIdx.x;
    const float* X; __half* Y; int heads; float scale;
    if (t < QROPE_N) { X = Q; Y = Qh; heads = NH; scale = qscale; }
    else { t -= QROPE_N; if (t >= KROPE_N) return; X = K; Y = Kh; heads = NKV; scale = 1.f; }
    int d = t & 127;
    int s = (t >> 7) & (SS - 1);
    int rest = t >> 18;
    int hh = rest % heads;
    int b  = rest / heads;
    float p = (float)pos_ids[b * SS + s];
    float inv = exp2f((float)d * NEG_L2F);
    float ang = p * inv;
    float si, co;
    sincosf(ang, &si, &co);
    size_t base = (((size_t)b * heads + hh) * SS + s) * HD;
    float x1 = X[base + d], x2 = X[base + d + 128];
    Y[base + d]       = __float2half((x1 * co - x2 * si) * scale);
    Y[base + d + 128] = __float2half((x2 * co + x1 * si) * scale);
}

// ------------------------- tensor-core flash attention ----------------------
__device__ __forceinline__ void cp_att_wait1() {
    asm volatile("cp.async.wait_group 1;" ::: "memory");
}
__device__ __forceinline__ void load_tile_async(uint32_t sdst, const __half* g, int tid) {
#pragma unroll
    for (int i = 0; i < 16; i++) {
        int idx = i * 128 + tid;
        int row = idx >> 5;
        int d = (idx & 31) * 8;
        cp_async16(sdst + tile_off(row, d), g + row * HD + d);
    }
}

__global__ __launch_bounds__(128, 2) void attn_tc(
    const __half* __restrict__ Qh,
    const __half* __restrict__ Kh, const __half* __restrict__ Vh,
    __half* __restrict__ A2O)
{
    extern __shared__ char dsm[];
    uint32_t raw = smem_u32(dsm);
    uint32_t sb = (raw + 1023u) & ~1023u;
    const uint32_t sQh = sb, sKh = sb + 32768, sVh = sb + 65536;

    const int tid = threadIdx.x;
    const int wid = tid >> 5;
    const int lane = tid & 31;
    const int qblk = blockIdx.x;
    const int h = blockIdx.y;
    const int b = blockIdx.z;
    const int kv = h >> 1;
    const int warpM = wid * 16;

    const __half* qhp = Qh + (((size_t)(b * NH + h)) * SS + qblk * 64) * HD;
    const __half* khp = Kh + ((size_t)(b * NKV + kv)) * SS * HD;
    const __half* vhp = Vh + ((size_t)(b * NKV + kv)) * SS * HD;

    int lo = qblk * 64 - (WIN - 1);
    if (lo < 0) lo = 0;
    lo &= ~63;
    const int hi = qblk * 64;

    load_tile_async(sQh, qhp, tid);
    load_tile_async(sKh, khp + (size_t)lo * HD, tid);
    cp_commit();
    load_tile_async(sVh, vhp + (size_t)lo * HD, tid);
    cp_commit();

    float oacc[32][4];
#pragma unroll
    for (int i = 0; i < 32; i++)
#pragma unroll
        for (int j = 0; j < 4; j++) oacc[i][j] = 0.f;
    float m0 = -1e30f, m1 = -1e30f, l0 = 0.f, l1 = 0.f;

    const int lrow = lane & 15;
    const int lhalf = (lane >> 4) * 16;
    const int qi = qblk * 64 + warpM + (lane >> 2);

    for (int kt = lo; kt <= hi; kt += 64) {
        cp_att_wait1();
        __syncthreads();

        float sacc[8][4];
#pragma unroll
        for (int i = 0; i < 8; i++)
#pragma unroll
            for (int j = 0; j < 4; j++) sacc[i][j] = 0.f;

#pragma unroll
        for (int kc = 0; kc < 16; kc++) {
            const int c = kc >> 2;
            const int colb = (kc & 3) * 32 + lhalf;
            uint32_t aqh[4];
            uint32_t aoff = (uint32_t)(c * 8192) + SWZ((uint32_t)((warpM + lrow) * 128 + colb));
            ldsm4(aqh, sQh + aoff);
#pragma unroll
            for (int g = 0; g < 4; g++) {
                uint32_t boff = (uint32_t)(c * 8192) + SWZ((uint32_t)((g * 16 + lrow) * 128 + colb));
                uint32_t bh[4];
                ldsm4(bh, sKh + boff);
                mma16816h(sacc[2 * g],     aqh, bh[0], bh[2]);
                mma16816h(sacc[2 * g + 1], aqh, bh[1], bh[3]);
            }
        }
        __syncthreads();
        if (kt + 64 <= hi)
            load_tile_async(sKh, khp + (size_t)(kt + 64) * HD, tid);
        cp_commit();

        float tm0 = -1e30f, tm1 = -1e30f;
#pragma unroll
        for (int nt = 0; nt < 8; nt++) {
#pragma unroll
            for (int j = 0; j < 4; j++) {
                int kj = kt + nt * 8 + (lane & 3) * 2 + (j & 1);
                int row = qi + ((j >> 1) * 8);
                float x = sacc[nt][j];
                float e = __expf(2.f * x);
                float s = 50.f * __fdividef(e - 1.f, e + 1.f);
                bool ok = (kj <= row) && (row - kj < WIN);
                s = ok ? s : -1e30f;
                sacc[nt][j] = s;
                if (j < 2) tm0 = fmaxf(tm0, s); else tm1 = fmaxf(tm1, s);
            }
        }
        tm0 = fmaxf(tm0, __shfl_xor_sync(0xffffffffu, tm0, 1));
        tm0 = fmaxf(tm0, __shfl_xor_sync(0xffffffffu, tm0, 2));
        tm1 = fmaxf(tm1, __shfl_xor_sync(0xffffffffu, tm1, 1));
        tm1 = fmaxf(tm1, __shfl_xor_sync(0xffffffffu, tm1, 2));

        float mn0 = fmaxf(m0, tm0), mn1 = fmaxf(m1, tm1);
        float al0 = __expf(m0 - mn0), al1 = __expf(m1 - mn1);
        m0 = mn0; m1 = mn1;

        float rs0 = 0.f, rs1 = 0.f;
#pragma unroll
        for (int nt = 0; nt < 8; nt++) {
            float p0 = __expf(sacc[nt][0] - mn0);
            float p1 = __expf(sacc[nt][1] - mn0);
            float p2 = __expf(sacc[nt][2] - mn1);
            float p3 = __expf(sacc[nt][3] - mn1);
            sacc[nt][0] = p0; sacc[nt][1] = p1; sacc[nt][2] = p2; sacc[nt][3] = p3;
            rs0 += p0 + p1; rs1 += p2 + p3;
        }
        rs0 += __shfl_xor_sync(0xffffffffu, rs0, 1);
        rs0 += __shfl_xor_sync(0xffffffffu, rs0, 2);
        rs1 += __shfl_xor_sync(0xffffffffu, rs1, 1);
        rs1 += __shfl_xor_sync(0xffffffffu, rs1, 2);
        l0 = l0 * al0 + rs0;
        l1 = l1 * al1 + rs1;

        uint32_t aP[4][4];
#pragma unroll
        for (int kc2 = 0; kc2 < 4; kc2++) {
            aP[kc2][0] = h2u(__floats2half2_rn(sacc[2 * kc2][0],     sacc[2 * kc2][1]));
            aP[kc2][1] = h2u(__floats2half2_rn(sacc[2 * kc2][2],     sacc[2 * kc2][3]));
            aP[kc2][2] = h2u(__floats2half2_rn(sacc[2 * kc2 + 1][0], sacc[2 * kc2 + 1][1]));
            aP[kc2][3] = h2u(__floats2half2_rn(sacc[2 * kc2 + 1][2], sacc[2 * kc2 + 1][3]));
        }

#pragma unroll
        for (int dt = 0; dt < 32; dt++) {
            oacc[dt][0] *= al0; oacc[dt][1] *= al0;
            oacc[dt][2] *= al1; oacc[dt][3] *= al1;
        }

        cp_att_wait1();
        __syncthreads();

#pragma unroll
        for (int kc2 = 0; kc2 < 4; kc2++) {
#pragma unroll
            for (int dg = 0; dg < 16; dg++) {
                int key = kc2 * 16 + lrow;
                int d = dg * 16 + (lane >> 4) * 8;
                uint32_t r[4];
                ldsm4t(r, sVh + tile_off(key, d));
                mma16816h(oacc[dg * 2],     aP[kc2], r[0], r[1]);
                mma16816h(oacc[dg * 2 + 1], aP[kc2], r[2], r[3]);
            }
        }
        __syncthreads();
        if (kt + 64 <= hi)
            load_tile_async(sVh, vhp + (size_t)(kt + 64) * HD, tid);
        cp_commit();
    }

    float il0 = __fdividef(1.f, l0);
    float il1 = __fdividef(1.f, l1);
    __half* a0 = A2O + ((size_t)(b * SS + qi)) * KO + h * HD;
    __half* a1 = A2O + ((size_t)(b * SS + qi + 8)) * KO + h * HD;
    int cbase = (lane & 3) * 2;
#pragma unroll
    for (int dt = 0; dt < 32; dt++) {
        int col = dt * 8 + cbase;
        *(__half2*)&a0[col] = __floats2half2_rn(oacc[dt][0] * il0, oacc[dt][1] * il0);
        *(__half2*)&a1[col] = __floats2half2_rn(oacc[dt][2] * il1, oacc[dt][3] * il1);
    }
}

// ---------------------------------------------------------------------------
extern "C" void kernel_launch(void* const* d_in, const int* in_sizes, int n_in,
                              void* d_out, int out_size)
{
    const float* hid = (const float*)d_in[0];
    const int*   pos = (const int*)d_in[2];
    const float* Wq  = (const float*)d_in[3];
    const float* Wk  = (const float*)d_in[4];
    const float* Wv  = (const float*)d_in[5];
    const float* Wo  = (const float*)d_in[6];
    float* out = (float*)d_out;

    float *qp, *kp;
    __half *a2, *b2, *a2o, *b2o, *qh_, *kh_, *vh_;
    cudaGetSymbolAddress((void**)&qp,  g_q);
    cudaGetSymbolAddress((void**)&kp,  g_k);
    cudaGetSymbolAddress((void**)&a2,  g_a2);
    cudaGetSymbolAddress((void**)&b2,  g_b2);
    cudaGetSymbolAddress((void**)&a2o, g_a2o);
    cudaGetSymbolAddress((void**)&b2o, g_b2o);
    cudaGetSymbolAddress((void**)&qh_, g_qh);
    cudaGetSymbolAddress((void**)&kh_, g_kh);
    cudaGetSymbolAddress((void**)&vh_, g_vh);

    cudaFuncSetAttribute(gemm_tc, cudaFuncAttributeMaxDynamicSharedMemorySize, GEMM_SMEM);
    cudaFuncSetAttribute(attn_tc, cudaFuncAttributeMaxDynamicSharedMemorySize, ATT_SMEM);

    // ---- single stream; fused prep kernels ----
    conv_half4<<<(MROWS*HH/4 + 255)/256, 256>>>(hid, a2, MROWS*HH/4);
    transp_qkv<<<dim3(128, HH/32), 256>>>(Wq, Wk, Wv, b2);

    gemm_tc<<<dim3(NQKV/128, MROWS/128), 256, GEMM_SMEM>>>(a2, b2, qp, kp, vh_, HH, 1, 0);

    rope_fused<<<(QROPE_N + KROPE_N + 255)/256, 256>>>(qp, qh_, kp, kh_, pos, 1.f/(16.f*50.f));

    attn_tc<<<dim3(SS/64, NH, BB), 128, ATT_SMEM>>>(qh_, kh_, vh_, a2o);

    transp_h<<<dim3(HH/32, 2048/32), 256>>>(Wo, b2o, 2048, HH);
    gemm_tc<<<dim3(HH/128, MROWS/128), 256, GEMM_SMEM>>>(a2o, b2o, out, nullptr, nullptr, KO, 0, HH);
}